// round 1
// baseline (speedup 1.0000x reference)
#include <cuda_runtime.h>
#include <cstdint>

#define N_IMG 32
#define C_IN  128
#define H_DIM 56
#define W_DIM 56
#define P_OUT 128
#define HP (H_DIM + 2)
#define WP (W_DIM + 2)
#define BN_EPS 1e-5f

// Scratch (allocation-free rule: __device__ globals)
__device__ uint4  g_apack[N_IMG * HP * WP];   // packed activations, zero-padded border, 1.72 MB
__device__ uint4  g_wpack[P_OUT * 9];         // packed weights per tap (4 x u32 = 128 ch)
__device__ int    g_corr[P_OUT * 8];          // border-correction values per out-channel
__device__ float2 g_sc[P_OUT];                // (scale, offset) for fused bias+BN

// ---------------------------------------------------------------------------
// Pack weights: binarize, popcount-encode, compute tap weight-sums for the
// zero-padding correction, and fold bias+BN into one (scale, offset) pair.
// ---------------------------------------------------------------------------
__global__ void pack_w_kernel(const float* __restrict__ w,
                              const float* __restrict__ bias,
                              const float* __restrict__ gamma,
                              const float* __restrict__ beta,
                              const float* __restrict__ rmean,
                              const float* __restrict__ rvar) {
    int p = threadIdx.x;
    if (p >= P_OUT) return;

    int ws[9];
    #pragma unroll
    for (int t = 0; t < 9; t++) {
        int kh = t / 3, kw = t % 3;
        unsigned int words[4] = {0u, 0u, 0u, 0u};
        for (int c = 0; c < C_IN; c++) {
            float v = w[((p * C_IN + c) * 3 + kh) * 3 + kw];
            words[c >> 5] |= (unsigned int)(v >= 0.0f) << (c & 31);
        }
        g_wpack[p * 9 + t] = make_uint4(words[0], words[1], words[2], words[3]);
        int pc = __popc(words[0]) + __popc(words[1]) + __popc(words[2]) + __popc(words[3]);
        ws[t] = 2 * pc - C_IN;   // sum over channels of sign(w) for this tap
    }
    // invalid-tap sums: rows, cols, corners (inclusion-exclusion)
    g_corr[p * 8 + 0] = ws[0] + ws[1] + ws[2];   // top row    (h == 0)
    g_corr[p * 8 + 1] = ws[6] + ws[7] + ws[8];   // bottom row (h == H-1)
    g_corr[p * 8 + 2] = ws[0] + ws[3] + ws[6];   // left col   (w == 0)
    g_corr[p * 8 + 3] = ws[2] + ws[5] + ws[8];   // right col  (w == W-1)
    g_corr[p * 8 + 4] = ws[0];                   // top-left corner
    g_corr[p * 8 + 5] = ws[2];                   // top-right
    g_corr[p * 8 + 6] = ws[6];                   // bottom-left
    g_corr[p * 8 + 7] = ws[8];                   // bottom-right

    float inv = gamma[p] / sqrtf(rvar[p] + BN_EPS);
    float offs = bias[p] * inv + beta[p] - rmean[p] * inv;
    g_sc[p] = make_float2(inv, offs);
}

// ---------------------------------------------------------------------------
// Pack activations: sign-binarize x (NCHW) into 128-bit pixel words, with a
// 1-pixel zero border. One block per (n, padded-row); lane = padded column.
// Global reads coalesced (lanes sweep w at fixed c).
// ---------------------------------------------------------------------------
__global__ void pack_a_kernel(const float* __restrict__ x) {
    int b = blockIdx.x;
    int n = b / HP;
    int hp = b % HP;
    int wp = threadIdx.x;
    if (wp >= WP) return;

    uint4 out = make_uint4(0u, 0u, 0u, 0u);
    if (hp >= 1 && hp <= H_DIM && wp >= 1 && wp <= W_DIM) {
        int h = hp - 1, w = wp - 1;
        const float* base = x + (size_t)n * C_IN * H_DIM * W_DIM + h * W_DIM + w;
        unsigned int words[4] = {0u, 0u, 0u, 0u};
        #pragma unroll 8
        for (int c = 0; c < C_IN; c++) {
            float v = base[(size_t)c * H_DIM * W_DIM];
            words[c >> 5] |= (unsigned int)(v >= 0.0f) << (c & 31);
        }
        out = make_uint4(words[0], words[1], words[2], words[3]);
    }
    g_apack[(n * HP + hp) * WP + wp] = out;
}

// ---------------------------------------------------------------------------
// Fused XNOR-popcount conv + bias + BN + residual.
// One block per (image, output row). 256 threads: lane w = t & 63 (pad 56->64),
// channel group cg = t >> 6 (4 groups x 32 channels).
// Each thread keeps its 9-tap / 36-word activation window in registers and
// sweeps 32 output channels; weight LDS is warp-uniform (broadcast).
// ---------------------------------------------------------------------------
__global__ void __launch_bounds__(256)
conv_kernel(const float* __restrict__ x, float* __restrict__ out) {
    __shared__ uint4  s_act[3 * WP];       // 174 * 16 B
    __shared__ uint4  s_w[P_OUT * 9];      // 18 KB
    __shared__ int    s_corr[P_OUT * 8];   // 4 KB
    __shared__ float2 s_sc[P_OUT];         // 1 KB

    int b = blockIdx.x;
    int n = b / H_DIM;
    int h = b % H_DIM;
    int t = threadIdx.x;

    for (int i = t; i < P_OUT * 9; i += 256) s_w[i] = g_wpack[i];
    for (int i = t; i < P_OUT * 8; i += 256) s_corr[i] = g_corr[i];
    for (int i = t; i < P_OUT; i += 256)     s_sc[i] = g_sc[i];
    for (int i = t; i < 3 * WP; i += 256)
        s_act[i] = g_apack[(n * HP + h + i / WP) * WP + (i % WP)];
    __syncthreads();

    int w = t & 63;
    int cg = t >> 6;
    if (w >= W_DIM) return;

    // 3x3 taps, 4 words each, held in registers
    unsigned int xa[36];
    #pragma unroll
    for (int dr = 0; dr < 3; dr++) {
        #pragma unroll
        for (int dc = 0; dc < 3; dc++) {
            uint4 v = s_act[dr * WP + w + dc];
            int k = (dr * 3 + dc) * 4;
            xa[k + 0] = v.x; xa[k + 1] = v.y; xa[k + 2] = v.z; xa[k + 3] = v.w;
        }
    }

    // border correction coefficients (inclusion-exclusion)
    int ft = (h == 0), fb = (h == H_DIM - 1);
    int fl = (w == 0), fr = (w == W_DIM - 1);
    int cf0 = ft, cf1 = fb, cf2 = fl, cf3 = fr;
    int cf4 = -(ft & fl), cf5 = -(ft & fr), cf6 = -(fb & fl), cf7 = -(fb & fr);

    const float* xin = x + ((size_t)(n * P_OUT + cg * 32) * H_DIM + h) * W_DIM + w;
    float* ob = out + ((size_t)(n * P_OUT + cg * 32) * H_DIM + h) * W_DIM + w;
    const size_t cstride = (size_t)H_DIM * W_DIM;

    #pragma unroll 2
    for (int i = 0; i < 32; i++) {
        int p = cg * 32 + i;
        int pcsum = 0;
        #pragma unroll
        for (int tp = 0; tp < 9; tp++) {
            uint4 wv = s_w[p * 9 + tp];
            pcsum += __popc(xa[tp * 4 + 0] ^ wv.x)
                   + __popc(xa[tp * 4 + 1] ^ wv.y)
                   + __popc(xa[tp * 4 + 2] ^ wv.z)
                   + __popc(xa[tp * 4 + 3] ^ wv.w);
        }
        int dot = 9 * C_IN - 2 * pcsum;     // raw dot with zero-pad bias

        const int* cr = &s_corr[p * 8];
        dot += cf0 * cr[0] + cf1 * cr[1] + cf2 * cr[2] + cf3 * cr[3]
             + cf4 * cr[4] + cf5 * cr[5] + cf6 * cr[6] + cf7 * cr[7];

        float2 sc = s_sc[p];
        ob[i * cstride] = (float)dot * sc.x + sc.y + xin[i * cstride];
    }
}

// ---------------------------------------------------------------------------
extern "C" void kernel_launch(void* const* d_in, const int* in_sizes, int n_in,
                              void* d_out, int out_size) {
    const float* x     = (const float*)d_in[0];
    const float* w     = (const float*)d_in[1];
    const float* bias  = (const float*)d_in[2];
    const float* gamma = (const float*)d_in[3];
    const float* beta  = (const float*)d_in[4];
    const float* rmean = (const float*)d_in[5];
    const float* rvar  = (const float*)d_in[6];
    float* out = (float*)d_out;

    pack_w_kernel<<<1, 128>>>(w, bias, gamma, beta, rmean, rvar);
    pack_a_kernel<<<N_IMG * HP, 64>>>(x);
    conv_kernel<<<N_IMG * H_DIM, 256>>>(x, out);
}

// round 2
// speedup vs baseline: 1.3335x; 1.3335x over previous
#include <cuda_runtime.h>
#include <cstdint>

#define N_IMG 32
#define C_IN  128
#define H_DIM 56
#define W_DIM 56
#define P_OUT 128
#define HP (H_DIM + 2)
#define WP (W_DIM + 2)
#define BN_EPS 1e-5f
#define R_ROWS 4

// Scratch (allocation-free rule: __device__ globals)
__device__ uint4    g_apack[N_IMG * HP * WP];   // packed activations, zero border
__device__ unsigned g_wpack32[P_OUT * 48];      // weights: [p][word u][tap t, padded 9->12]
__device__ int      g_corr[P_OUT * 8];          // border-correction values per out-channel
__device__ float2   g_sc[P_OUT];                // (scale, offset) fused bias+BN

// full adder: sum of three bit-vectors -> sum (w1) + carry (w2). 2 LOP3s.
__device__ __forceinline__ void fa(unsigned a, unsigned b, unsigned c,
                                   unsigned &s, unsigned &cy) {
    s  = a ^ b ^ c;                       // LOP3 0x96
    cy = (a & b) | (a & c) | (b & c);     // LOP3 0xE8 (majority)
}

// ---------------------------------------------------------------------------
// Pack weights (parallel): one block per output channel, ballot-based packing.
// ---------------------------------------------------------------------------
__global__ void pack_w_kernel(const float* __restrict__ w,
                              const float* __restrict__ bias,
                              const float* __restrict__ gamma,
                              const float* __restrict__ beta,
                              const float* __restrict__ rmean,
                              const float* __restrict__ rvar) {
    int p = blockIdx.x;           // 0..127
    int c = threadIdx.x;          // 0..127 (input channel)
    int lane = c & 31, wd = c >> 5;

    __shared__ unsigned sw[9][4];
    __shared__ int ssum[9];

    #pragma unroll
    for (int t = 0; t < 9; t++) {
        float v = w[(size_t)(p * C_IN + c) * 9 + t];
        unsigned m = __ballot_sync(0xffffffffu, v >= 0.0f);
        if (lane == 0) sw[t][wd] = m;
    }
    __syncthreads();

    if (c < 9) {
        int t = c;
        int pc = __popc(sw[t][0]) + __popc(sw[t][1]) + __popc(sw[t][2]) + __popc(sw[t][3]);
        ssum[t] = 2 * pc - C_IN;
    }
    if (c < 36) {
        int u = c / 9, t = c % 9;
        g_wpack32[p * 48 + u * 12 + t] = sw[t][u];
    }
    __syncthreads();

    if (c == 0) {
        const int* ws = ssum;
        g_corr[p * 8 + 0] = ws[0] + ws[1] + ws[2];   // top row
        g_corr[p * 8 + 1] = ws[6] + ws[7] + ws[8];   // bottom row
        g_corr[p * 8 + 2] = ws[0] + ws[3] + ws[6];   // left col
        g_corr[p * 8 + 3] = ws[2] + ws[5] + ws[8];   // right col
        g_corr[p * 8 + 4] = ws[0];                   // corners
        g_corr[p * 8 + 5] = ws[2];
        g_corr[p * 8 + 6] = ws[6];
        g_corr[p * 8 + 7] = ws[8];

        float inv = gamma[p] / sqrtf(rvar[p] + BN_EPS);
        float offs = bias[p] * inv + beta[p] - rmean[p] * inv;
        g_sc[p] = make_float2(inv, offs);
    }
}

// ---------------------------------------------------------------------------
// Pack activations with 1-pixel zero border (same as round 1; memory-bound).
// ---------------------------------------------------------------------------
__global__ void pack_a_kernel(const float* __restrict__ x) {
    int b = blockIdx.x;
    int n = b / HP;
    int hp = b % HP;
    int wp = threadIdx.x;
    if (wp >= WP) return;

    uint4 out = make_uint4(0u, 0u, 0u, 0u);
    if (hp >= 1 && hp <= H_DIM && wp >= 1 && wp <= W_DIM) {
        int h = hp - 1, w = wp - 1;
        const float* base = x + (size_t)n * C_IN * H_DIM * W_DIM + h * W_DIM + w;
        unsigned int words[4] = {0u, 0u, 0u, 0u};
        #pragma unroll 8
        for (int c = 0; c < C_IN; c++) {
            float v = base[(size_t)c * H_DIM * W_DIM];
            words[c >> 5] |= (unsigned int)(v >= 0.0f) << (c & 31);
        }
        out = make_uint4(words[0], words[1], words[2], words[3]);
    }
    g_apack[(n * HP + hp) * WP + wp] = out;
}

// ---------------------------------------------------------------------------
// Fused XNOR conv + bias + BN + residual with CSA popcount compression.
// 224 threads = 4 channel groups x 56 lanes (no padding waste).
// Each block handles R_ROWS output rows of one image.
// ---------------------------------------------------------------------------
__global__ void __launch_bounds__(224)
conv_kernel(const float* __restrict__ x, float* __restrict__ out) {
    __shared__ __align__(16) unsigned s_w[P_OUT * 48];   // 24 KB
    __shared__ uint4  s_act[(R_ROWS + 2) * WP];          // 5.4 KB
    __shared__ int    s_corr[P_OUT * 8];                 // 4 KB
    __shared__ float2 s_sc[P_OUT];                       // 1 KB

    int b = blockIdx.x;
    int n = b / (H_DIM / R_ROWS);
    int h0 = (b % (H_DIM / R_ROWS)) * R_ROWS;
    int t = threadIdx.x;

    for (int i = t; i < P_OUT * 48; i += 224) s_w[i] = g_wpack32[i];
    for (int i = t; i < P_OUT * 8;  i += 224) s_corr[i] = g_corr[i];
    for (int i = t; i < P_OUT;      i += 224) s_sc[i] = g_sc[i];
    for (int i = t; i < (R_ROWS + 2) * WP; i += 224)
        s_act[i] = g_apack[(n * HP + h0 + i / WP) * WP + (i % WP)];
    __syncthreads();

    int cg = t / 56;
    int w  = t % 56;
    int pbase = cg * 32;
    const size_t cstride = (size_t)H_DIM * W_DIM;

    for (int r = 0; r < R_ROWS; r++) {
        int h = h0 + r;

        // 3x3 taps x 4 words, registers; xa[tap*4 + word]
        unsigned xa[36];
        #pragma unroll
        for (int dr = 0; dr < 3; dr++) {
            #pragma unroll
            for (int dc = 0; dc < 3; dc++) {
                uint4 v = s_act[(r + dr) * WP + w + dc];
                int k = (dr * 3 + dc) * 4;
                xa[k + 0] = v.x; xa[k + 1] = v.y; xa[k + 2] = v.z; xa[k + 3] = v.w;
            }
        }

        int ft = (h == 0), fb = (h == H_DIM - 1);
        int fl = (w == 0), fr = (w == W_DIM - 1);
        int cf0 = ft, cf1 = fb, cf2 = fl, cf3 = fr;
        int cf4 = -(ft & fl), cf5 = -(ft & fr), cf6 = -(fb & fl), cf7 = -(fb & fr);

        const float* xin = x   + ((size_t)(n * P_OUT + pbase) * H_DIM + h) * W_DIM + w;
        float*       ob  = out + ((size_t)(n * P_OUT + pbase) * H_DIM + h) * W_DIM + w;

        #pragma unroll 2
        for (int i = 0; i < 32; i++) {
            int p = pbase + i;
            const unsigned* wb = &s_w[p * 48];

            int p1 = 0, p2 = 0, p4 = 0;
            #pragma unroll
            for (int u = 0; u < 4; u++) {
                uint4 wa = *(const uint4*)&wb[u * 12];       // taps 0..3
                uint4 wc = *(const uint4*)&wb[u * 12 + 4];   // taps 4..7
                unsigned w8 = wb[u * 12 + 8];                // tap 8

                unsigned t0 = xa[ 0 + u] ^ wa.x;
                unsigned t1 = xa[ 4 + u] ^ wa.y;
                unsigned t2 = xa[ 8 + u] ^ wa.z;
                unsigned t3 = xa[12 + u] ^ wa.w;
                unsigned t4 = xa[16 + u] ^ wc.x;
                unsigned t5 = xa[20 + u] ^ wc.y;
                unsigned t6 = xa[24 + u] ^ wc.z;
                unsigned t7 = xa[28 + u] ^ wc.w;
                unsigned t8 = xa[32 + u] ^ w8;

                unsigned s1a, c1a, s1b, c1b, s1c, c1c;
                fa(t0, t1, t2, s1a, c1a);
                fa(t3, t4, t5, s1b, c1b);
                fa(t6, t7, t8, s1c, c1c);
                unsigned S1, C2a, S2, C4;
                fa(s1a, s1b, s1c, S1, C2a);     // w1 + w2
                fa(c1a, c1b, c1c, S2, C4);      // w2 + w4

                p1 += __popc(S1);
                p2 += __popc(C2a) + __popc(S2);
                p4 += __popc(C4);
            }
            int pcsum = p1 + 2 * p2 + 4 * p4;
            int dot = 9 * C_IN - 2 * pcsum;

            const int* cr = &s_corr[p * 8];
            dot += cf0 * cr[0] + cf1 * cr[1] + cf2 * cr[2] + cf3 * cr[3]
                 + cf4 * cr[4] + cf5 * cr[5] + cf6 * cr[6] + cf7 * cr[7];

            float2 sc = s_sc[p];
            ob[i * cstride] = (float)dot * sc.x + sc.y + xin[i * cstride];
        }
    }
}

// ---------------------------------------------------------------------------
extern "C" void kernel_launch(void* const* d_in, const int* in_sizes, int n_in,
                              void* d_out, int out_size) {
    const float* x     = (const float*)d_in[0];
    const float* w     = (const float*)d_in[1];
    const float* bias  = (const float*)d_in[2];
    const float* gamma = (const float*)d_in[3];
    const float* beta  = (const float*)d_in[4];
    const float* rmean = (const float*)d_in[5];
    const float* rvar  = (const float*)d_in[6];
    float* out = (float*)d_out;

    pack_w_kernel<<<P_OUT, 128>>>(w, bias, gamma, beta, rmean, rvar);
    pack_a_kernel<<<N_IMG * HP, 64>>>(x);
    conv_kernel<<<N_IMG * (H_DIM / R_ROWS), 224>>>(x, out);
}

// round 3
// speedup vs baseline: 1.5258x; 1.1442x over previous
#include <cuda_runtime.h>
#include <cstdint>

#define N_IMG 32
#define C_IN  128
#define H_DIM 56
#define W_DIM 56
#define P_OUT 128
#define HP (H_DIM + 2)
#define WP (W_DIM + 2)
#define BN_EPS 1e-5f

// Scratch (allocation-free rule: __device__ globals)
__device__ uint4  g_apack[N_IMG * HP * WP];   // packed activations, zero border
__device__ uint4  g_wpack[P_OUT * 9];         // packed weights per tap (4 x u32)
__device__ int    g_corr[P_OUT * 8];          // border-correction values per out-channel
__device__ float2 g_sc[P_OUT];                // (scale, offset) fused bias+BN

// ---------------------------------------------------------------------------
// Pack weights (parallel): one block per output channel, ballot-based packing.
// ---------------------------------------------------------------------------
__global__ void pack_w_kernel(const float* __restrict__ w,
                              const float* __restrict__ bias,
                              const float* __restrict__ gamma,
                              const float* __restrict__ beta,
                              const float* __restrict__ rmean,
                              const float* __restrict__ rvar) {
    int p = blockIdx.x;           // 0..127
    int c = threadIdx.x;          // 0..127 (input channel)
    int lane = c & 31, wd = c >> 5;

    __shared__ unsigned sw[9][4];
    __shared__ int ssum[9];

    #pragma unroll
    for (int t = 0; t < 9; t++) {
        float v = w[(size_t)(p * C_IN + c) * 9 + t];
        unsigned m = __ballot_sync(0xffffffffu, v >= 0.0f);
        if (lane == 0) sw[t][wd] = m;
    }
    __syncthreads();

    if (c < 9) {
        int t = c;
        int pc = __popc(sw[t][0]) + __popc(sw[t][1]) + __popc(sw[t][2]) + __popc(sw[t][3]);
        ssum[t] = 2 * pc - C_IN;
    }
    __syncthreads();

    if (c < 9) {
        g_wpack[p * 9 + c] = make_uint4(sw[c][0], sw[c][1], sw[c][2], sw[c][3]);
    }
    if (c == 0) {
        const int* ws = ssum;
        g_corr[p * 8 + 0] = ws[0] + ws[1] + ws[2];   // top row
        g_corr[p * 8 + 1] = ws[6] + ws[7] + ws[8];   // bottom row
        g_corr[p * 8 + 2] = ws[0] + ws[3] + ws[6];   // left col
        g_corr[p * 8 + 3] = ws[2] + ws[5] + ws[8];   // right col
        g_corr[p * 8 + 4] = ws[0];                   // corners
        g_corr[p * 8 + 5] = ws[2];
        g_corr[p * 8 + 6] = ws[6];
        g_corr[p * 8 + 7] = ws[8];

        float inv = gamma[p] / sqrtf(rvar[p] + BN_EPS);
        float offs = bias[p] * inv + beta[p] - rmean[p] * inv;
        g_sc[p] = make_float2(inv, offs);
    }
}

// ---------------------------------------------------------------------------
// Pack activations with 1-pixel zero border.
// ---------------------------------------------------------------------------
__global__ void pack_a_kernel(const float* __restrict__ x) {
    int b = blockIdx.x;
    int n = b / HP;
    int hp = b % HP;
    int wp = threadIdx.x;
    if (wp >= WP) return;

    uint4 out = make_uint4(0u, 0u, 0u, 0u);
    if (hp >= 1 && hp <= H_DIM && wp >= 1 && wp <= W_DIM) {
        int h = hp - 1, w = wp - 1;
        const float* base = x + (size_t)n * C_IN * H_DIM * W_DIM + h * W_DIM + w;
        unsigned int words[4] = {0u, 0u, 0u, 0u};
        #pragma unroll 8
        for (int c = 0; c < C_IN; c++) {
            float v = base[(size_t)c * H_DIM * W_DIM];
            words[c >> 5] |= (unsigned int)(v >= 0.0f) << (c & 31);
        }
        out = make_uint4(words[0], words[1], words[2], words[3]);
    }
    g_apack[(n * HP + hp) * WP + wp] = out;
}

// ---------------------------------------------------------------------------
// Fused XNOR conv + bias + BN + residual. Plain XOR+POPC (POPC is ~full-rate
// on sm_103a). Each thread computes TWO vertically-adjacent output pixels so
// weight LDS is amortized 2x and there are two independent popc chains.
// 256 threads: lane w = t & 63 (pad 56->64), channel group cg = t >> 6.
// Warp-uniform weight addresses -> LDS.128 broadcast.
// ---------------------------------------------------------------------------
__global__ void __launch_bounds__(256)
conv_kernel(const float* __restrict__ x, float* __restrict__ out) {
    __shared__ uint4  s_act[4 * WP];       // 3.7 KB (rows h0-1 .. h0+2 padded)
    __shared__ uint4  s_w[P_OUT * 9];      // 18 KB
    __shared__ int    s_corr[P_OUT * 8];   // 4 KB
    __shared__ float2 s_sc[P_OUT];         // 1 KB

    int b = blockIdx.x;
    int n = b / (H_DIM / 2);
    int h0 = (b % (H_DIM / 2)) * 2;        // first of two output rows
    int t = threadIdx.x;

    for (int i = t; i < P_OUT * 9; i += 256) s_w[i] = g_wpack[i];
    for (int i = t; i < P_OUT * 8; i += 256) s_corr[i] = g_corr[i];
    for (int i = t; i < P_OUT;     i += 256) s_sc[i] = g_sc[i];
    for (int i = t; i < 4 * WP;    i += 256)
        s_act[i] = g_apack[(n * HP + h0 + i / WP) * WP + (i % WP)];
    __syncthreads();

    int w = t & 63;
    int cg = t >> 6;
    if (w >= W_DIM) return;

    // 4 rows x 3 cols of packed activations in registers: xa[row][col*4+u]
    unsigned xa[4][12];
    #pragma unroll
    for (int dr = 0; dr < 4; dr++) {
        #pragma unroll
        for (int dc = 0; dc < 3; dc++) {
            uint4 v = s_act[dr * WP + w + dc];
            xa[dr][dc * 4 + 0] = v.x; xa[dr][dc * 4 + 1] = v.y;
            xa[dr][dc * 4 + 2] = v.z; xa[dr][dc * 4 + 3] = v.w;
        }
    }

    // border flags for the two rows
    int ft0 = (h0 == 0);              // row h0 top
    int fb1 = (h0 + 1 == H_DIM - 1);  // row h0+1 bottom
    int fl = (w == 0), fr = (w == W_DIM - 1);

    const size_t cstride = (size_t)H_DIM * W_DIM;
    const float* xin0 = x   + ((size_t)(n * P_OUT + cg * 32) * H_DIM + h0) * W_DIM + w;
    float*       ob0  = out + ((size_t)(n * P_OUT + cg * 32) * H_DIM + h0) * W_DIM + w;

    #pragma unroll 2
    for (int i = 0; i < 32; i++) {
        int p = cg * 32 + i;
        int acc0 = 0, acc1 = 0;
        #pragma unroll
        for (int tp = 0; tp < 9; tp++) {
            int dr = tp / 3, dc = tp % 3;
            uint4 wv = s_w[p * 9 + tp];
            acc0 += __popc(xa[dr    ][dc * 4 + 0] ^ wv.x)
                  + __popc(xa[dr    ][dc * 4 + 1] ^ wv.y)
                  + __popc(xa[dr    ][dc * 4 + 2] ^ wv.z)
                  + __popc(xa[dr    ][dc * 4 + 3] ^ wv.w);
            acc1 += __popc(xa[dr + 1][dc * 4 + 0] ^ wv.x)
                  + __popc(xa[dr + 1][dc * 4 + 1] ^ wv.y)
                  + __popc(xa[dr + 1][dc * 4 + 2] ^ wv.z)
                  + __popc(xa[dr + 1][dc * 4 + 3] ^ wv.w);
        }
        int dot0 = 9 * C_IN - 2 * acc0;
        int dot1 = 9 * C_IN - 2 * acc1;

        const int* cr = &s_corr[p * 8];
        // row h0: may be top; never bottom (h0 even, <= 54)
        dot0 += ft0 * cr[0] + fl * cr[2] + fr * cr[3]
              - (ft0 & fl) * cr[4] - (ft0 & fr) * cr[5];
        // row h0+1: may be bottom; never top (h0+1 >= 1)
        dot1 += fb1 * cr[1] + fl * cr[2] + fr * cr[3]
              - (fb1 & fl) * cr[6] - (fb1 & fr) * cr[7];

        float2 sc = s_sc[p];
        ob0[i * cstride]         = (float)dot0 * sc.x + sc.y + xin0[i * cstride];
        ob0[i * cstride + W_DIM] = (float)dot1 * sc.x + sc.y + xin0[i * cstride + W_DIM];
    }
}

// ---------------------------------------------------------------------------
extern "C" void kernel_launch(void* const* d_in, const int* in_sizes, int n_in,
                              void* d_out, int out_size) {
    const float* x     = (const float*)d_in[0];
    const float* w     = (const float*)d_in[1];
    const float* bias  = (const float*)d_in[2];
    const float* gamma = (const float*)d_in[3];
    const float* beta  = (const float*)d_in[4];
    const float* rmean = (const float*)d_in[5];
    const float* rvar  = (const float*)d_in[6];
    float* out = (float*)d_out;

    pack_w_kernel<<<P_OUT, 128>>>(w, bias, gamma, beta, rmean, rvar);
    pack_a_kernel<<<N_IMG * HP, 64>>>(x);
    conv_kernel<<<N_IMG * (H_DIM / 2), 256>>>(x, out);
}

// round 4
// speedup vs baseline: 1.6266x; 1.0660x over previous
#include <cuda_runtime.h>
#include <cstdint>

#define N_IMG 32
#define C_IN  128
#define H_DIM 56
#define W_DIM 56
#define P_OUT 128
#define HP (H_DIM + 2)
#define WP (W_DIM + 2)
#define BN_EPS 1e-5f

// Scratch (allocation-free rule: __device__ globals)
__device__ uint4  g_apack[N_IMG * HP * WP];   // packed activations, zero border
__device__ uint4  g_wpack[P_OUT * 9];         // packed weights per tap (4 x u32)
__device__ int    g_corr[P_OUT * 8];          // border-correction values per out-channel
__device__ float2 g_sc[P_OUT];                // (scale, offset) fused bias+BN

// full adder: sum of three bit-vectors -> sum (w1) + carry (w2). 2 LOP3s.
__device__ __forceinline__ void fa(unsigned a, unsigned b, unsigned c,
                                   unsigned &s, unsigned &cy) {
    s  = a ^ b ^ c;                       // LOP3 0x96
    cy = (a & b) | (a & c) | (b & c);     // LOP3 0xE8 (majority)
}

// 9-input CSA popcount: taps t[0..8] -> sum of set bits with only 4 POPCs.
__device__ __forceinline__ int popc9(const unsigned* t, int &p1, int &p2, int &p4) {
    unsigned s1a, c1a, s1b, c1b, s1c, c1c;
    fa(t[0], t[1], t[2], s1a, c1a);
    fa(t[3], t[4], t[5], s1b, c1b);
    fa(t[6], t[7], t[8], s1c, c1c);
    unsigned S1, C2a, S2, C4;
    fa(s1a, s1b, s1c, S1, C2a);     // weight 1 + weight 2
    fa(c1a, c1b, c1c, S2, C4);      // weight 2 + weight 4
    p1 += __popc(S1);
    p2 += __popc(C2a) + __popc(S2);
    p4 += __popc(C4);
    return 0;
}

// ---------------------------------------------------------------------------
// Pack weights (parallel): one block per output channel, ballot-based packing.
// ---------------------------------------------------------------------------
__global__ void pack_w_kernel(const float* __restrict__ w,
                              const float* __restrict__ bias,
                              const float* __restrict__ gamma,
                              const float* __restrict__ beta,
                              const float* __restrict__ rmean,
                              const float* __restrict__ rvar) {
    int p = blockIdx.x;           // 0..127
    int c = threadIdx.x;          // 0..127 (input channel)
    int lane = c & 31, wd = c >> 5;

    __shared__ unsigned sw[9][4];
    __shared__ int ssum[9];

    #pragma unroll
    for (int t = 0; t < 9; t++) {
        float v = w[(size_t)(p * C_IN + c) * 9 + t];
        unsigned m = __ballot_sync(0xffffffffu, v >= 0.0f);
        if (lane == 0) sw[t][wd] = m;
    }
    __syncthreads();

    if (c < 9) {
        int t = c;
        int pc = __popc(sw[t][0]) + __popc(sw[t][1]) + __popc(sw[t][2]) + __popc(sw[t][3]);
        ssum[t] = 2 * pc - C_IN;
    }
    __syncthreads();

    if (c < 9) {
        g_wpack[p * 9 + c] = make_uint4(sw[c][0], sw[c][1], sw[c][2], sw[c][3]);
    }
    if (c == 0) {
        const int* ws = ssum;
        g_corr[p * 8 + 0] = ws[0] + ws[1] + ws[2];   // top row
        g_corr[p * 8 + 1] = ws[6] + ws[7] + ws[8];   // bottom row
        g_corr[p * 8 + 2] = ws[0] + ws[3] + ws[6];   // left col
        g_corr[p * 8 + 3] = ws[2] + ws[5] + ws[8];   // right col
        g_corr[p * 8 + 4] = ws[0];                   // corners
        g_corr[p * 8 + 5] = ws[2];
        g_corr[p * 8 + 6] = ws[6];
        g_corr[p * 8 + 7] = ws[8];

        float inv = gamma[p] / sqrtf(rvar[p] + BN_EPS);
        float offs = bias[p] * inv + beta[p] - rmean[p] * inv;
        g_sc[p] = make_float2(inv, offs);
    }
}

// ---------------------------------------------------------------------------
// Pack activations with 1-pixel zero border. 256 threads cover 4 padded rows.
// ---------------------------------------------------------------------------
__global__ void __launch_bounds__(256) pack_a_kernel(const float* __restrict__ x) {
    int b = blockIdx.x;                 // (n, row-quad)
    int rq = b % ((HP + 3) / 4);
    int n  = b / ((HP + 3) / 4);
    int hp = rq * 4 + (threadIdx.x >> 6);
    int wp = threadIdx.x & 63;
    if (hp >= HP || wp >= WP) return;

    uint4 out = make_uint4(0u, 0u, 0u, 0u);
    if (hp >= 1 && hp <= H_DIM && wp >= 1 && wp <= W_DIM) {
        int h = hp - 1, w = wp - 1;
        const float* base = x + (size_t)n * C_IN * H_DIM * W_DIM + h * W_DIM + w;
        unsigned int words[4] = {0u, 0u, 0u, 0u};
        #pragma unroll 8
        for (int c = 0; c < C_IN; c++) {
            float v = base[(size_t)c * H_DIM * W_DIM];
            words[c >> 5] |= (unsigned int)(v >= 0.0f) << (c & 31);
        }
        out = make_uint4(words[0], words[1], words[2], words[3]);
    }
    g_apack[(n * HP + hp) * WP + wp] = out;
}

// ---------------------------------------------------------------------------
// Fused XNOR conv + bias + BN + residual.
// CSA-compressed popcount (POPC is quarter-rate on sm_103a; CSA moves work to
// the full-rate LOP3 pipe). Warp-uniform weight LDS (w = t&63, cg = t>>6).
// Each thread computes TWO vertically-adjacent output pixels.
// ---------------------------------------------------------------------------
__global__ void __launch_bounds__(256)
conv_kernel(const float* __restrict__ x, float* __restrict__ out) {
    __shared__ uint4  s_act[4 * WP];       // 3.7 KB
    __shared__ uint4  s_w[P_OUT * 9];      // 18 KB
    __shared__ int    s_corr[P_OUT * 8];   // 4 KB
    __shared__ float2 s_sc[P_OUT];         // 1 KB

    int b = blockIdx.x;
    int n = b / (H_DIM / 2);
    int h0 = (b % (H_DIM / 2)) * 2;        // first of two output rows
    int t = threadIdx.x;

    for (int i = t; i < P_OUT * 9; i += 256) s_w[i] = g_wpack[i];
    for (int i = t; i < P_OUT * 8; i += 256) s_corr[i] = g_corr[i];
    for (int i = t; i < P_OUT;     i += 256) s_sc[i] = g_sc[i];
    for (int i = t; i < 4 * WP;    i += 256)
        s_act[i] = g_apack[(n * HP + h0 + i / WP) * WP + (i % WP)];
    __syncthreads();

    int w = t & 63;
    int cg = t >> 6;
    if (w >= W_DIM) return;

    // 4 rows x 3 cols of packed activations in registers: xa[row][col*4+u]
    unsigned xa[4][12];
    #pragma unroll
    for (int dr = 0; dr < 4; dr++) {
        #pragma unroll
        for (int dc = 0; dc < 3; dc++) {
            uint4 v = s_act[dr * WP + w + dc];
            xa[dr][dc * 4 + 0] = v.x; xa[dr][dc * 4 + 1] = v.y;
            xa[dr][dc * 4 + 2] = v.z; xa[dr][dc * 4 + 3] = v.w;
        }
    }

    int ft0 = (h0 == 0);              // row h0 may be top
    int fb1 = (h0 + 1 == H_DIM - 1);  // row h0+1 may be bottom
    int fl = (w == 0), fr = (w == W_DIM - 1);

    const size_t cstride = (size_t)H_DIM * W_DIM;
    const float* xin0 = x   + ((size_t)(n * P_OUT + cg * 32) * H_DIM + h0) * W_DIM + w;
    float*       ob0  = out + ((size_t)(n * P_OUT + cg * 32) * H_DIM + h0) * W_DIM + w;

    #pragma unroll 2
    for (int i = 0; i < 32; i++) {
        int p = cg * 32 + i;

        // load 9 weight vectors (warp-uniform -> broadcast LDS.128)
        unsigned wv[9][4];
        #pragma unroll
        for (int tp = 0; tp < 9; tp++) {
            uint4 v = s_w[p * 9 + tp];
            wv[tp][0] = v.x; wv[tp][1] = v.y; wv[tp][2] = v.z; wv[tp][3] = v.w;
        }

        int p1a = 0, p2a = 0, p4a = 0;   // row h0
        int p1b = 0, p2b = 0, p4b = 0;   // row h0+1
        #pragma unroll
        for (int u = 0; u < 4; u++) {
            unsigned ta[9], tb[9];
            #pragma unroll
            for (int tp = 0; tp < 9; tp++) {
                int dr = tp / 3, dc = tp % 3;
                ta[tp] = xa[dr    ][dc * 4 + u] ^ wv[tp][u];
                tb[tp] = xa[dr + 1][dc * 4 + u] ^ wv[tp][u];
            }
            popc9(ta, p1a, p2a, p4a);
            popc9(tb, p1b, p2b, p4b);
        }
        int dot0 = 9 * C_IN - 2 * (p1a + 2 * p2a + 4 * p4a);
        int dot1 = 9 * C_IN - 2 * (p1b + 2 * p2b + 4 * p4b);

        const int* cr = &s_corr[p * 8];
        dot0 += ft0 * cr[0] + fl * cr[2] + fr * cr[3]
              - (ft0 & fl) * cr[4] - (ft0 & fr) * cr[5];
        dot1 += fb1 * cr[1] + fl * cr[2] + fr * cr[3]
              - (fb1 & fl) * cr[6] - (fb1 & fr) * cr[7];

        float2 sc = s_sc[p];
        ob0[i * cstride]         = (float)dot0 * sc.x + sc.y + xin0[i * cstride];
        ob0[i * cstride + W_DIM] = (float)dot1 * sc.x + sc.y + xin0[i * cstride + W_DIM];
    }
}

// ---------------------------------------------------------------------------
extern "C" void kernel_launch(void* const* d_in, const int* in_sizes, int n_in,
                              void* d_out, int out_size) {
    const float* x     = (const float*)d_in[0];
    const float* w     = (const float*)d_in[1];
    const float* bias  = (const float*)d_in[2];
    const float* gamma = (const float*)d_in[3];
    const float* beta  = (const float*)d_in[4];
    const float* rmean = (const float*)d_in[5];
    const float* rvar  = (const float*)d_in[6];
    float* out = (float*)d_out;

    pack_w_kernel<<<P_OUT, 128>>>(w, bias, gamma, beta, rmean, rvar);
    pack_a_kernel<<<N_IMG * ((HP + 3) / 4), 256>>>(x);
    conv_kernel<<<N_IMG * (H_DIM / 2), 256>>>(x, out);
}